// round 1
// baseline (speedup 1.0000x reference)
#include <cuda_runtime.h>
#include <cstdint>

// Max problem size this buffer supports: B=32, N=1024
#define MAXQ 4096
static __device__ float g_tmp[32u * 1024u * 1024u];   // stage-1 intermediate [b][ny][qx]

// Per-query precomputed params
static __device__ int   g_Ix[MAXQ];
static __device__ float4 g_cx[MAXQ];   // (c0, c1, c2, unused) for x-stage
static __device__ int   g_Iy[MAXQ];
static __device__ float4 g_dy[MAXQ];   // (h0, h1, h2, h3*r) for y-stage

// Exact replica of jnp.searchsorted(axis[1:-1], v, side='left')
__device__ __forceinline__ int lower_bound_inner(const float* __restrict__ axis, int N, float v) {
    int lo = 0, hi = N - 2;               // searching axis[1 .. N-2]
    while (lo < hi) {
        int mid = (lo + hi) >> 1;
        if (axis[1 + mid] < v) lo = mid + 1; else hi = mid;
    }
    return lo;
}

__global__ void precompute_kernel(const float* __restrict__ xaxis,
                                  const float* __restrict__ yaxis,
                                  const float* __restrict__ xs,
                                  const float* __restrict__ ys,
                                  int N) {
    int q = blockIdx.x * blockDim.x + threadIdx.x;
    if (q >= N) return;
    // ---- x queries ----
    {
        float v = xs[q];
        int I = lower_bound_inner(xaxis, N, v);
        float x0 = xaxis[I], x1 = xaxis[I + 1], x2 = xaxis[I + 2];
        float dx = x1 - x0;
        float t = (v - x0) / dx;
        float t2 = t * t, t3 = t2 * t;
        float h0 = 1.0f - 3.0f * t2 + 2.0f * t3;
        float h1 = t - 2.0f * t2 + t3;
        float h2 = 3.0f * t2 - 2.0f * t3;
        float h3 = t3 - t2;
        float r = dx / (x2 - x1);
        g_Ix[q] = I;
        g_cx[q] = make_float4(h0 - h1, h1 + h2 - h3 * r, h3 * r, 0.0f);
    }
    // ---- y queries ----
    {
        float v = ys[q];
        int I = lower_bound_inner(yaxis, N, v);
        float y0 = yaxis[I], y1 = yaxis[I + 1], y2 = yaxis[I + 2];
        float dy = y1 - y0;
        float t = (v - y0) / dy;
        float t2 = t * t, t3 = t2 * t;
        float h0 = 1.0f - 3.0f * t2 + 2.0f * t3;
        float h1 = t - 2.0f * t2 + t3;
        float h2 = 3.0f * t2 - 2.0f * t3;
        float h3 = t3 - t2;
        float r = dy / (y2 - y1);
        g_Iy[q] = I;
        g_dy[q] = make_float4(h0, h1, h2, h3 * r);
    }
}

// Stage 1: x-interp. One block per (b, ny) row of signal.
// tmp[b][ny][qx] = c0*S[b,ny,Ix] + c1*S[b,ny,Ix+1] + c2*S[b,ny,Ix+2]
__global__ __launch_bounds__(256) void stage1_kernel(const float* __restrict__ signal,
                                                     int N) {
    extern __shared__ float row[];
    size_t rbase = (size_t)blockIdx.x * N;
    const float4* src4 = reinterpret_cast<const float4*>(signal + rbase);
    float4* dst4 = reinterpret_cast<float4*>(g_tmp + rbase);
    int n4 = N >> 2;
    for (int i = threadIdx.x; i < n4; i += blockDim.x)
        reinterpret_cast<float4*>(row)[i] = src4[i];
    __syncthreads();
    for (int j = threadIdx.x; j < n4; j += blockDim.x) {
        float o[4];
        int qb = j << 2;
#pragma unroll
        for (int k = 0; k < 4; ++k) {
            int q = qb + k;
            int I = g_Ix[q];
            float4 c = g_cx[q];
            o[k] = c.x * row[I] + c.y * row[I + 1] + c.z * row[I + 2];
        }
        dst4[j] = make_float4(o[0], o[1], o[2], o[3]);
    }
}

// Stage 2: y-interp. One block per (b, qy) output row. All streams coalesced.
// out[b][qy][qx] = d0*tmp[b,Iy,qx] + d2*tmp[b,Iy+1,qx]
//                + d1*(S[b,Iy+1,qx]-S[b,Iy,qx]) + d3*(S[b,Iy+2,qx]-S[b,Iy+1,qx])
__global__ __launch_bounds__(256) void stage2_kernel(const float* __restrict__ signal,
                                                     float* __restrict__ out,
                                                     int N) {
    int b  = blockIdx.x / N;
    int qy = blockIdx.x - b * N;
    int Iy = g_Iy[qy];
    float4 d = g_dy[qy];
    size_t plane = (size_t)b * N * N;
    const float4* t0 = reinterpret_cast<const float4*>(g_tmp + plane + (size_t)Iy * N);
    const float4* t1 = reinterpret_cast<const float4*>(g_tmp + plane + (size_t)(Iy + 1) * N);
    const float4* s0 = reinterpret_cast<const float4*>(signal + plane + (size_t)Iy * N);
    const float4* s1 = reinterpret_cast<const float4*>(signal + plane + (size_t)(Iy + 1) * N);
    const float4* s2 = reinterpret_cast<const float4*>(signal + plane + (size_t)(Iy + 2) * N);
    float4* o4 = reinterpret_cast<float4*>(out + plane + (size_t)qy * N);
    int n4 = N >> 2;
    for (int j = threadIdx.x; j < n4; j += blockDim.x) {
        float4 a0 = t0[j], a1 = t1[j];
        float4 b0 = s0[j], b1 = s1[j], b2 = s2[j];
        float4 r;
        r.x = d.x * a0.x + d.z * a1.x + d.y * (b1.x - b0.x) + d.w * (b2.x - b1.x);
        r.y = d.x * a0.y + d.z * a1.y + d.y * (b1.y - b0.y) + d.w * (b2.y - b1.y);
        r.z = d.x * a0.z + d.z * a1.z + d.y * (b1.z - b0.z) + d.w * (b2.z - b1.z);
        r.w = d.x * a0.w + d.z * a1.w + d.y * (b1.w - b0.w) + d.w * (b2.w - b1.w);
        o4[j] = r;
    }
}

extern "C" void kernel_launch(void* const* d_in, const int* in_sizes, int n_in,
                              void* d_out, int out_size) {
    const float* xaxis  = (const float*)d_in[0];
    const float* yaxis  = (const float*)d_in[1];
    const float* signal = (const float*)d_in[2];
    const float* xs     = (const float*)d_in[3];
    const float* ys     = (const float*)d_in[4];
    float* out = (float*)d_out;

    int N = in_sizes[0];                       // 1024
    int B = (int)((long long)in_sizes[2] / ((long long)N * N));  // 32

    precompute_kernel<<<(N + 255) / 256, 256>>>(xaxis, yaxis, xs, ys, N);
    stage1_kernel<<<B * N, 256, N * sizeof(float)>>>(signal, N);
    stage2_kernel<<<B * N, 256>>>(signal, out, N);
}

// round 2
// speedup vs baseline: 1.1997x; 1.1997x over previous
#include <cuda_runtime.h>
#include <cstdint>

#define MAXQ 4096
// Packed per-query params
static __device__ float4 g_px[MAXQ];   // (c0, c1, c2, Ix as float bits) for x-stage
static __device__ int    g_Iy[MAXQ];
static __device__ float4 g_dy[MAXQ];   // (h0, h1, h2, h3*r) for y-stage

// Exact replica of jnp.searchsorted(axis[1:-1], v, side='left')
__device__ __forceinline__ int lower_bound_inner(const float* __restrict__ axis, int N, float v) {
    int lo = 0, hi = N - 2;               // searching axis[1 .. N-2]
    while (lo < hi) {
        int mid = (lo + hi) >> 1;
        if (axis[1 + mid] < v) lo = mid + 1; else hi = mid;
    }
    return lo;
}

__global__ void precompute_kernel(const float* __restrict__ xaxis,
                                  const float* __restrict__ yaxis,
                                  const float* __restrict__ xs,
                                  const float* __restrict__ ys,
                                  int N) {
    int q = blockIdx.x * blockDim.x + threadIdx.x;
    if (q >= N) return;
    // ---- x queries: fold Hermite basis + slope terms into 3-tap stencil ----
    {
        float v = xs[q];
        int I = lower_bound_inner(xaxis, N, v);
        float x0 = xaxis[I], x1 = xaxis[I + 1], x2 = xaxis[I + 2];
        float dx = x1 - x0;
        float t = (v - x0) / dx;
        float t2 = t * t, t3 = t2 * t;
        float h0 = 1.0f - 3.0f * t2 + 2.0f * t3;
        float h1 = t - 2.0f * t2 + t3;
        float h2 = 3.0f * t2 - 2.0f * t3;
        float h3 = t3 - t2;
        float r = dx / (x2 - x1);
        g_px[q] = make_float4(h0 - h1, h1 + h2 - h3 * r, h3 * r, __int_as_float(I));
    }
    // ---- y queries ----
    {
        float v = ys[q];
        int I = lower_bound_inner(yaxis, N, v);
        float y0 = yaxis[I], y1 = yaxis[I + 1], y2 = yaxis[I + 2];
        float dy = y1 - y0;
        float t = (v - y0) / dy;
        float t2 = t * t, t3 = t2 * t;
        float h0 = 1.0f - 3.0f * t2 + 2.0f * t3;
        float h1 = t - 2.0f * t2 + t3;
        float h2 = 3.0f * t2 - 2.0f * t3;
        float h3 = t3 - t2;
        float r = dy / (y2 - y1);
        g_Iy[q] = I;
        g_dy[q] = make_float4(h0, h1, h2, h3 * r);
    }
}

// Fully fused: one block per output row (b, qy).
// out[b][qy][qx] = d0 * X(S[Iy,:])[qx] + d2 * X(S[Iy+1,:])[qx]
//                + d1*(S[Iy+1,qx]-S[Iy,qx]) + d3*(S[Iy+2,qx]-S[Iy+1,qx])
// where X(row)[qx] = c0*row[Ix] + c1*row[Ix+1] + c2*row[Ix+2].
// Rows Iy, Iy+1 are staged interleaved in smem so both x-interps share one
// float2 gather per tap. Row Iy+2 is only needed column-aligned -> coalesced
// global float4 read (L2-hot).
__global__ __launch_bounds__(256) void fused_kernel(const float* __restrict__ signal,
                                                    float* __restrict__ out,
                                                    int N) {
    extern __shared__ float2 pair[];   // N entries: (S[Iy][i], S[Iy+1][i])
    int b  = blockIdx.x / N;
    int qy = blockIdx.x - b * N;
    int Iy = g_Iy[qy];
    float4 d = g_dy[qy];
    size_t plane = (size_t)b * N * N;
    const float* __restrict__ r0 = signal + plane + (size_t)Iy * N;
    const float* __restrict__ r1 = r0 + N;
    const float* __restrict__ r2 = r1 + N;

    for (int i = threadIdx.x; i < N; i += blockDim.x)
        pair[i] = make_float2(__ldg(r0 + i), __ldg(r1 + i));
    __syncthreads();

    float4* __restrict__ o4 = reinterpret_cast<float4*>(out + plane + (size_t)qy * N);
    const float4* __restrict__ r2v = reinterpret_cast<const float4*>(r2);
    int n4 = N >> 2;
    for (int j = threadIdx.x; j < n4; j += blockDim.x) {
        float4 s2v = __ldg(r2v + j);
        int qb = j << 2;
        float res[4];
#pragma unroll
        for (int k = 0; k < 4; ++k) {
            int q = qb + k;
            float4 p = g_px[q];
            int I = __float_as_int(p.w);
            float2 a = pair[I];
            float2 bb = pair[I + 1];
            float2 c = pair[I + 2];
            float x0 = p.x * a.x + p.y * bb.x + p.z * c.x;   // X(S[Iy])[q]
            float x1 = p.x * a.y + p.y * bb.y + p.z * c.y;   // X(S[Iy+1])[q]
            float2 pc = pair[q];                              // S[Iy][q], S[Iy+1][q]
            float s2 = (k == 0) ? s2v.x : (k == 1) ? s2v.y : (k == 2) ? s2v.z : s2v.w;
            res[k] = d.x * x0 + d.z * x1 + d.y * (pc.y - pc.x) + d.w * (s2 - pc.y);
        }
        o4[j] = make_float4(res[0], res[1], res[2], res[3]);
    }
}

extern "C" void kernel_launch(void* const* d_in, const int* in_sizes, int n_in,
                              void* d_out, int out_size) {
    const float* xaxis  = (const float*)d_in[0];
    const float* yaxis  = (const float*)d_in[1];
    const float* signal = (const float*)d_in[2];
    const float* xs     = (const float*)d_in[3];
    const float* ys     = (const float*)d_in[4];
    float* out = (float*)d_out;

    int N = in_sizes[0];                       // 1024
    int B = (int)((long long)in_sizes[2] / ((long long)N * N));  // 32

    precompute_kernel<<<(N + 127) / 128, 128>>>(xaxis, yaxis, xs, ys, N);
    fused_kernel<<<B * N, 256, N * sizeof(float2)>>>(signal, out, N);
}

// round 3
// speedup vs baseline: 1.5623x; 1.3023x over previous
#include <cuda_runtime.h>
#include <cstdint>

#define MAXQ 4096
#define TPB 256
#define MAXIT 8   // supports N up to TPB*MAXIT = 2048

// Packed per-query params
static __device__ float4 g_px[MAXQ];   // (c0, c1, c2, Ix as float bits) for x-stage
static __device__ int    g_Iy[MAXQ];
static __device__ float4 g_dy[MAXQ];   // (h0, h1, h2, h3*r) for y-stage

// Exact replica of jnp.searchsorted(axis[1:-1], v, side='left')
__device__ __forceinline__ int lower_bound_inner(const float* __restrict__ axis, int N, float v) {
    int lo = 0, hi = N - 2;               // searching axis[1 .. N-2]
    while (lo < hi) {
        int mid = (lo + hi) >> 1;
        if (axis[1 + mid] < v) lo = mid + 1; else hi = mid;
    }
    return lo;
}

__global__ void precompute_kernel(const float* __restrict__ xaxis,
                                  const float* __restrict__ yaxis,
                                  const float* __restrict__ xs,
                                  const float* __restrict__ ys,
                                  int N) {
    int q = blockIdx.x * blockDim.x + threadIdx.x;
    if (q >= N) return;
    // ---- x queries: fold Hermite basis + slope terms into 3-tap stencil ----
    {
        float v = xs[q];
        int I = lower_bound_inner(xaxis, N, v);
        float x0 = xaxis[I], x1 = xaxis[I + 1], x2 = xaxis[I + 2];
        float dx = x1 - x0;
        float t = (v - x0) / dx;
        float t2 = t * t, t3 = t2 * t;
        float h0 = 1.0f - 3.0f * t2 + 2.0f * t3;
        float h1 = t - 2.0f * t2 + t3;
        float h2 = 3.0f * t2 - 2.0f * t3;
        float h3 = t3 - t2;
        float r = dx / (x2 - x1);
        g_px[q] = make_float4(h0 - h1, h1 + h2 - h3 * r, h3 * r, __int_as_float(I));
    }
    // ---- y queries ----
    {
        float v = ys[q];
        int I = lower_bound_inner(yaxis, N, v);
        float y0 = yaxis[I], y1 = yaxis[I + 1], y2 = yaxis[I + 2];
        float dy = y1 - y0;
        float t = (v - y0) / dy;
        float t2 = t * t, t3 = t2 * t;
        float h0 = 1.0f - 3.0f * t2 + 2.0f * t3;
        float h1 = t - 2.0f * t2 + t3;
        float h2 = 3.0f * t2 - 2.0f * t3;
        float h3 = t3 - t2;
        float r = dy / (y2 - y1);
        g_Iy[q] = I;
        g_dy[q] = make_float4(h0, h1, h2, h3 * r);
    }
}

// Fully fused: one block per output row (b, qy).
// out[b][qy][qx] = d0 * X(S[Iy,:])[qx] + d2 * X(S[Iy+1,:])[qx]
//                + d1*(S[Iy+1,qx]-S[Iy,qx]) + d3*(S[Iy+2,qx]-S[Iy+1,qx])
// where X(row)[qx] = c0*row[Ix] + c1*row[Ix+1] + c2*row[Ix+2].
//
// Lane-contiguous scalar mapping q = tid + TPB*it:
//  - every structured access (params, fill, s2, out) is perfectly coalesced
//  - fill and compute touch identical q per thread -> column values stay
//    in registers across the sync (no pair[q] LDS at all)
//  - only the 3 x-gather LDS.64 remain irregular (irreducible)
__global__ __launch_bounds__(TPB) void fused_kernel(const float* __restrict__ signal,
                                                    float* __restrict__ out,
                                                    int N) {
    extern __shared__ float2 pair[];   // N entries: (S[Iy][i], S[Iy+1][i])
    int b  = blockIdx.x / N;
    int qy = blockIdx.x - b * N;
    int Iy = g_Iy[qy];
    float4 d = g_dy[qy];
    size_t plane = (size_t)b * N * N;
    const float* __restrict__ r0 = signal + plane + (size_t)Iy * N;
    const float* __restrict__ r1 = r0 + N;
    const float* __restrict__ r2 = r1 + N;
    float* __restrict__ orow = out + plane + (size_t)qy * N;

    int iters = N / TPB;                // 4 for N=1024
    float v0[MAXIT], v1[MAXIT];

#pragma unroll
    for (int it = 0; it < MAXIT; ++it) {
        if (it >= iters) break;
        int q = threadIdx.x + it * TPB;
        float a = __ldg(r0 + q);
        float bb = __ldg(r1 + q);
        v0[it] = a; v1[it] = bb;
        pair[q] = make_float2(a, bb);
    }
    __syncthreads();

#pragma unroll
    for (int it = 0; it < MAXIT; ++it) {
        if (it >= iters) break;
        int q = threadIdx.x + it * TPB;
        float4 p = g_px[q];
        int I = __float_as_int(p.w);
        float2 a  = pair[I];
        float2 bb = pair[I + 1];
        float2 c  = pair[I + 2];
        float x0 = p.x * a.x + p.y * bb.x + p.z * c.x;   // X(S[Iy])[q]
        float x1 = p.x * a.y + p.y * bb.y + p.z * c.y;   // X(S[Iy+1])[q]
        float s2 = __ldg(r2 + q);
        orow[q] = d.x * x0 + d.z * x1 + d.y * (v1[it] - v0[it]) + d.w * (s2 - v1[it]);
    }
}

extern "C" void kernel_launch(void* const* d_in, const int* in_sizes, int n_in,
                              void* d_out, int out_size) {
    const float* xaxis  = (const float*)d_in[0];
    const float* yaxis  = (const float*)d_in[1];
    const float* signal = (const float*)d_in[2];
    const float* xs     = (const float*)d_in[3];
    const float* ys     = (const float*)d_in[4];
    float* out = (float*)d_out;

    int N = in_sizes[0];                       // 1024
    int B = (int)((long long)in_sizes[2] / ((long long)N * N));  // 32

    precompute_kernel<<<(N + 127) / 128, 128>>>(xaxis, yaxis, xs, ys, N);
    fused_kernel<<<B * N, TPB, N * sizeof(float2)>>>(signal, out, N);
}